// round 5
// baseline (speedup 1.0000x reference)
#include <cuda_runtime.h>
#include <cuda_bf16.h>
#include <cstdint>

#define B_  4
#define S_  2048
#define DM_ 512
#define H_  8
#define D_  64
#define K3_ 1536            // 3x hi/lo expanded K
#define NCHUNK 24           // K3_/64

// ================= helpers =================
__device__ __forceinline__ uint32_t smem_u32(const void* p) {
    uint32_t a;
    asm("{ .reg .u64 t; cvta.to.shared.u64 t, %1; cvt.u32.u64 %0, t; }" : "=r"(a) : "l"(p));
    return a;
}
#define SWZ128(off) ((off) ^ (((off) >> 3) & 0x70))

__device__ __forceinline__ void cp_async16(uint32_t dst, const void* src) {
    asm volatile("cp.async.cg.shared.global [%0], [%1], 16;" :: "r"(dst), "l"(src));
}
__device__ __forceinline__ void cp_async16z(uint32_t dst, const void* src, uint32_t n) {
    asm volatile("cp.async.cg.shared.global [%0], [%1], 16, %2;" :: "r"(dst), "l"(src), "r"(n));
}
#define CP_COMMIT() asm volatile("cp.async.commit_group;" ::: "memory")
#define CP_WAIT(n)  asm volatile("cp.async.wait_group %0;" :: "n"(n) : "memory")

__device__ __forceinline__ void ldmx4(uint32_t& r0, uint32_t& r1, uint32_t& r2, uint32_t& r3,
                                      uint32_t addr) {
    asm volatile("ldmatrix.sync.aligned.m8n8.x4.shared.b16 {%0,%1,%2,%3}, [%4];"
                 : "=r"(r0), "=r"(r1), "=r"(r2), "=r"(r3) : "r"(addr));
}
__device__ __forceinline__ void mma16816(float* c, const uint32_t* a, uint32_t b0, uint32_t b1) {
    asm volatile(
        "mma.sync.aligned.m16n8k16.row.col.f32.bf16.bf16.f32 "
        "{%0,%1,%2,%3}, {%4,%5,%6,%7}, {%8,%9}, {%0,%1,%2,%3};"
        : "+f"(c[0]), "+f"(c[1]), "+f"(c[2]), "+f"(c[3])
        : "r"(a[0]), "r"(a[1]), "r"(a[2]), "r"(a[3]), "r"(b0), "r"(b1));
}
__device__ __forceinline__ void split2(float f, __nv_bfloat16& hi, __nv_bfloat16& lo) {
    hi = __float2bfloat16(f);
    lo = __float2bfloat16(f - __bfloat162float(hi));
}
// pack a pair of fp32 into 3 u32 (6 bf16) triplets
__device__ __forceinline__ void packA(float a, float b, uint32_t* w) {  // (hi,lo,hi)
    __nv_bfloat16 h0, l0, h1, l1; split2(a, h0, l0); split2(b, h1, l1);
    const uint32_t H0 = __bfloat16_as_ushort(h0), L0 = __bfloat16_as_ushort(l0);
    const uint32_t H1 = __bfloat16_as_ushort(h1), L1 = __bfloat16_as_ushort(l1);
    w[0] = H0 | (L0 << 16); w[1] = H0 | (H1 << 16); w[2] = L1 | (H1 << 16);
}
__device__ __forceinline__ void packB(float a, float b, uint32_t* w) {  // (hi,hi,lo)
    __nv_bfloat16 h0, l0, h1, l1; split2(a, h0, l0); split2(b, h1, l1);
    const uint32_t H0 = __bfloat16_as_ushort(h0), L0 = __bfloat16_as_ushort(l0);
    const uint32_t H1 = __bfloat16_as_ushort(h1), L1 = __bfloat16_as_ushort(l1);
    w[0] = H0 | (H0 << 16); w[1] = L0 | (H1 << 16); w[2] = H1 | (L1 << 16);
}

// ================= scratch =================
__device__ float g_v[B_ * S_ * DM_];
__device__ float g_part[B_ * 64 * DM_];
__device__ float g_vmean[B_ * DM_];
__device__ __nv_bfloat16 g_x3[B_ * S_ * K3_];        // x triplets, later ctx triplets
__device__ __nv_bfloat16 g_q3[B_ * S_ * K3_];        // q triplets (pattern A)
__device__ __nv_bfloat16 g_k3[B_ * S_ * K3_];        // k triplets (pattern B)
__device__ __nv_bfloat16 g_w3t[4 * DM_ * K3_];       // weights (pattern B), [N,K3]
__device__ __nv_bfloat16 g_v3t[2048 * 6912];         // V dims-major triplets, token-padded [-128,2176)

// ================= split kernels =================
__global__ __launch_bounds__(256) void split_act3(const float* __restrict__ X,
                                                  __nv_bfloat16* __restrict__ X3) {
    const int idx = blockIdx.x * 256 + threadIdx.x;
    const int m = idx >> 6, g = idx & 63;
    const float4 f0 = *(const float4*)(X + (size_t)m * 512 + g * 8);
    const float4 f1 = *(const float4*)(X + (size_t)m * 512 + g * 8 + 4);
    float v[8] = {f0.x, f0.y, f0.z, f0.w, f1.x, f1.y, f1.z, f1.w};
    uint32_t w[12];
#pragma unroll
    for (int i = 0; i < 4; i++) packA(v[2 * i], v[2 * i + 1], w + 3 * i);
    uint4* dst = (uint4*)(X3 + (size_t)m * K3_ + g * 24);
    dst[0] = ((uint4*)w)[0]; dst[1] = ((uint4*)w)[1]; dst[2] = ((uint4*)w)[2];
}

// all 4 weights in one launch; grid.z selects weight
__global__ __launch_bounds__(1024) void split_w4(const float* __restrict__ W0,
                                                 const float* __restrict__ W1,
                                                 const float* __restrict__ W2,
                                                 const float* __restrict__ W3,
                                                 __nv_bfloat16* __restrict__ W3T) {
    __shared__ float t[32][33];
    const int z = blockIdx.z;
    const float* W = (z == 0) ? W0 : (z == 1) ? W1 : (z == 2) ? W2 : W3;
    const int k0 = blockIdx.y * 32, n0 = blockIdx.x * 32;
    const int tx = threadIdx.x, ty = threadIdx.y;
    t[ty][tx] = W[(size_t)(k0 + ty) * 512 + n0 + tx];
    __syncthreads();
    const float v = t[tx][ty];
    __nv_bfloat16 hi, lo; split2(v, hi, lo);
    __nv_bfloat16* dst = W3T + (size_t)z * DM_ * K3_ + (size_t)(n0 + ty) * K3_ + 3 * (k0 + tx);
    dst[0] = hi; dst[1] = hi; dst[2] = lo;
}

// ================= GEMM mainloop (shared between fp32-out and triplet-out) =================
#define GEMM_SMEM (3 * 32768 + 1024)

#define GEMM_MAINLOOP()                                                                   \
    extern __shared__ char smraw[];                                                       \
    const uint32_t sbase = (smem_u32(smraw) + 1023) & ~1023u;                             \
    const int tid = threadIdx.x;                                                          \
    const int wid = tid >> 5, lane = tid & 31;                                            \
    const int bm = blockIdx.x * 128, bn = blockIdx.y * 128;                               \
    const int wm0 = (wid & 1) * 64, wn0 = (wid >> 1) * 32;                                \
    const int l_isB = tid >> 7;                                                           \
    const int l_row = (tid & 127);                                                        \
    const __nv_bfloat16* l_src = (l_isB ? B3 + (size_t)(bn + l_row) * K3_                 \
                                        : A3 + (size_t)(bm + l_row) * K3_);               \
    const uint32_t l_dst = sbase + (l_isB ? 16384 : 0);                                   \
    float acc[4][4][4];                                                                   \
    _Pragma("unroll")                                                                     \
    for (int a = 0; a < 4; a++)                                                           \
        _Pragma("unroll")                                                                 \
        for (int b = 0; b < 4; b++)                                                       \
            _Pragma("unroll")                                                             \
            for (int c = 0; c < 4; c++) acc[a][b][c] = 0.f;                               \
    _Pragma("unroll")                                                                     \
    for (int c = 0; c < 3; c++) {                                                         \
        const uint32_t db = l_dst + c * 32768;                                            \
        const __nv_bfloat16* sp = l_src + c * 64;                                         \
        _Pragma("unroll")                                                                 \
        for (int seg = 0; seg < 8; seg++)                                                 \
            cp_async16(db + SWZ128(l_row * 128 + seg * 16), sp + seg * 8);                \
        CP_COMMIT();                                                                      \
    }                                                                                     \
    for (int c = 0; c < NCHUNK; c++) {                                                    \
        CP_WAIT(2);                                                                       \
        __syncthreads();                                                                  \
        const uint32_t abuf = sbase + (c % 3) * 32768;                                    \
        const uint32_t bbuf = abuf + 16384;                                               \
        _Pragma("unroll")                                                                 \
        for (int ks = 0; ks < 4; ks++) {                                                  \
            const int cb = ks * 32 + ((lane >> 4) * 16);                                  \
            uint32_t bf[2][4];                                                            \
            _Pragma("unroll")                                                             \
            for (int nh = 0; nh < 2; nh++) {                                              \
                const int r = wn0 + nh * 16 + (lane & 15);                                \
                ldmx4(bf[nh][0], bf[nh][1], bf[nh][2], bf[nh][3],                         \
                      bbuf + SWZ128(r * 128 + cb));                                       \
            }                                                                             \
            _Pragma("unroll")                                                             \
            for (int mf = 0; mf < 4; mf++) {                                              \
                uint32_t a[4];                                                            \
                const int r = wm0 + mf * 16 + (lane & 15);                                \
                ldmx4(a[0], a[1], a[2], a[3], abuf + SWZ128(r * 128 + cb));               \
                _Pragma("unroll")                                                         \
                for (int nf = 0; nf < 4; nf++) {                                          \
                    const uint32_t b0 = bf[nf >> 1][(nf & 1)];                            \
                    const uint32_t b1 = bf[nf >> 1][(nf & 1) + 2];                        \
                    mma16816(acc[mf][nf], a, b0, b1);                                     \
                }                                                                         \
            }                                                                             \
        }                                                                                 \
        __syncthreads();                                                                  \
        if (c + 3 < NCHUNK) {                                                             \
            const uint32_t db = l_dst + ((c + 3) % 3) * 32768;                            \
            const __nv_bfloat16* sp = l_src + (c + 3) * 64;                               \
            _Pragma("unroll")                                                             \
            for (int seg = 0; seg < 8; seg++)                                             \
                cp_async16(db + SWZ128(l_row * 128 + seg * 16), sp + seg * 8);            \
        }                                                                                 \
        CP_COMMIT();                                                                      \
    }                                                                                     \
    const int qr = lane >> 2, qc = (lane & 3) * 2;

// fp32 output (used for V projection and final output projection)
__global__ __launch_bounds__(256, 2) void gemm_mma(const __nv_bfloat16* __restrict__ A3,
                                                   const __nv_bfloat16* __restrict__ B3,
                                                   const float* __restrict__ bias,
                                                   float* __restrict__ C) {
    GEMM_MAINLOOP()
#pragma unroll
    for (int mf = 0; mf < 4; mf++) {
        const int row = bm + wm0 + mf * 16 + qr;
#pragma unroll
        for (int nf = 0; nf < 4; nf++) {
            const int col = bn + wn0 + nf * 8 + qc;
            const float b0 = bias[col], b1 = bias[col + 1];
            float2 lo, hi;
            lo.x = acc[mf][nf][0] + b0; lo.y = acc[mf][nf][1] + b1;
            hi.x = acc[mf][nf][2] + b0; hi.y = acc[mf][nf][3] + b1;
            *(float2*)(C + (size_t)row * 512 + col) = lo;
            *(float2*)(C + (size_t)(row + 8) * 512 + col) = hi;
        }
    }
}

// triplet output: PAT 0 = pattern A (hi,lo,hi) for Q; PAT 1 = pattern B (hi,hi,lo) for K
template<int PAT>
__global__ __launch_bounds__(256, 2) void gemm_tri(const __nv_bfloat16* __restrict__ A3,
                                                   const __nv_bfloat16* __restrict__ B3,
                                                   const float* __restrict__ bias,
                                                   __nv_bfloat16* __restrict__ T3) {
    GEMM_MAINLOOP()
    uint32_t* t32 = (uint32_t*)T3;
#pragma unroll
    for (int mf = 0; mf < 4; mf++) {
        const int row = bm + wm0 + mf * 16 + qr;
#pragma unroll
        for (int nf = 0; nf < 4; nf++) {
            const int col = bn + wn0 + nf * 8 + qc;
            const float b0 = bias[col], b1 = bias[col + 1];
            uint32_t w[3];
            const uint32_t idx0 = (uint32_t)row * 768 + (3 * col) / 2;
            const uint32_t idx1 = idx0 + 8 * 768;
            if (PAT == 0) packA(acc[mf][nf][0] + b0, acc[mf][nf][1] + b1, w);
            else          packB(acc[mf][nf][0] + b0, acc[mf][nf][1] + b1, w);
            t32[idx0] = w[0]; t32[idx0 + 1] = w[1]; t32[idx0 + 2] = w[2];
            if (PAT == 0) packA(acc[mf][nf][2] + b0, acc[mf][nf][3] + b1, w);
            else          packB(acc[mf][nf][2] + b0, acc[mf][nf][3] + b1, w);
            t32[idx1] = w[0]; t32[idx1 + 1] = w[1]; t32[idx1 + 2] = w[2];
        }
    }
}

// ================= V transpose->triplet build (dims-major, token-padded) =================
// v3t row = (b*8+h)*64 + d, 6912 elts (2304 tokens x3, token index shifted +128)
__global__ __launch_bounds__(256) void v3t_build(const float* __restrict__ V,
                                                 __nv_bfloat16* __restrict__ V3T) {
    __shared__ float tr[64][65];
    const int cx = blockIdx.x;           // 0..35 chunks of 64 tokens, token0 = cx*64-128
    const int h = blockIdx.y, b = blockIdx.z;
    const int tid = threadIdx.x;
    const int t0 = cx * 64 - 128;
    const bool inr = (t0 >= 0) && (t0 + 64 <= S_);

    if (inr) {
        const int i = tid >> 2, dg = tid & 3;
        const float* vrow = V + ((size_t)(b * S_ + t0 + i)) * DM_ + h * D_ + dg * 16;
#pragma unroll
        for (int u = 0; u < 4; u++) {
            float4 f = *(const float4*)(vrow + u * 4);
            tr[dg * 16 + u * 4 + 0][i] = f.x;
            tr[dg * 16 + u * 4 + 1][i] = f.y;
            tr[dg * 16 + u * 4 + 2][i] = f.z;
            tr[dg * 16 + u * 4 + 3][i] = f.w;
        }
        __syncthreads();
    }

    const int d = tid >> 2, jg = tid & 3;
    uint32_t w[24];
    if (inr) {
#pragma unroll
        for (int t = 0; t < 8; t++)
            packB(tr[d][jg * 16 + 2 * t], tr[d][jg * 16 + 2 * t + 1], w + 3 * t);
    } else {
#pragma unroll
        for (int t = 0; t < 24; t++) w[t] = 0;
    }
    uint4* dst = (uint4*)((char*)V3T + ((size_t)((b * 8 + h) * 64 + d) * 6912) * 2
                          + (size_t)cx * 384 + jg * 96);
#pragma unroll
    for (int u = 0; u < 6; u++) dst[u] = ((uint4*)w)[u];
}

// ================= V mean =================
__global__ void vmean_partial(const float* __restrict__ V, float* __restrict__ part) {
    const int b = blockIdx.y, sc = blockIdx.x, c = threadIdx.x;
    const float* p = V + ((size_t)b * S_ + sc * 32) * DM_ + c;
    float s = 0.f;
#pragma unroll 8
    for (int t = 0; t < 32; t++) s += p[(size_t)t * DM_];
    part[((size_t)b * 64 + sc) * DM_ + c] = s;
}
__global__ void vmean_final(const float* __restrict__ part, float* __restrict__ vm) {
    const int b = blockIdx.x, c = threadIdx.x;
    const float* p = part + (size_t)b * 64 * DM_ + c;
    float s = 0.f;
#pragma unroll
    for (int t = 0; t < 64; t++) s += p[(size_t)t * DM_];
    vm[b * DM_ + c] = s * (1.0f / 2048.0f);
}

// ================= HMMA banded attention, precomputed triplets =================
// smem: AQ3 (Q3/P3) 64x400B, AK3 buf0 64x400B, AV3 buf1 64x400B, S 64x325 f32, invl
#define AQ3 0
#define AK3 25600
#define AV3 51200
#define ASF 76800
#define AIL 160000
#define ATT_SMEM 160256

__global__ __launch_bounds__(256, 1) void attn_mma2(const __nv_bfloat16* __restrict__ Q3,
                                                    const __nv_bfloat16* __restrict__ K3,
                                                    const __nv_bfloat16* __restrict__ V3T,
                                                    const float* __restrict__ VMEAN,
                                                    const int* __restrict__ XLEN,
                                                    __nv_bfloat16* __restrict__ C3) {
    extern __shared__ char smc[];
    const uint32_t sb = smem_u32(smc);
    float* Ss = (float*)(smc + ASF);
    float* invl = (float*)(smc + AIL);

    const int tid = threadIdx.x;
    const int wid = tid >> 5, lane = tid & 31;
    const int q0 = blockIdx.x * 64;
    const int h = blockIdx.y;
    const int b = blockIdx.z;
    const int xl = XLEN[b];

    const int wm = (wid & 3) * 16;
    const int wn = (wid >> 2) * 32;
    const int qr = lane >> 2, qc = (lane & 3) * 2;
    const int kbase0 = q0 - 128;

    const int lrow = tid >> 2;            // 0..63
    const int lcs = (tid & 3) * 6;        // 6 segs of 16B each

    // ---- issue Q3 + K0 (group0), K1 (group1) ----
    {
        const char* qsrc = (const char*)Q3 + ((size_t)(b * S_ + q0 + lrow) * K3_ + h * 192) * 2;
#pragma unroll
        for (int u = 0; u < 6; u++)
            cp_async16(sb + AQ3 + lrow * 400 + (lcs + u) * 16, qsrc + (lcs + u) * 16);
    }
#pragma unroll
    for (int c = 0; c < 2; c++) {
        const int jabs = kbase0 + c * 64 + lrow;
        const bool valid = (jabs >= 0) && (jabs < S_);
        const char* ksrc = (const char*)K3 + ((size_t)(b * S_ + (valid ? jabs : 0)) * K3_ + h * 192) * 2;
        const uint32_t buf = sb + (c ? AV3 : AK3);
        const uint32_t n = valid ? 16u : 0u;
#pragma unroll
        for (int u = 0; u < 6; u++)
            cp_async16z(buf + lrow * 400 + (lcs + u) * 16, ksrc + (lcs + u) * 16, n);
        CP_COMMIT();
    }

    // ---- phase 1: energies ----
#pragma unroll
    for (int c = 0; c < 5; c++) {
        if (c < 4) { CP_WAIT(1); } else { CP_WAIT(0); }
        __syncthreads();
        const uint32_t kbuf = sb + ((c & 1) ? AV3 : AK3);
        const int kb = kbase0 + c * 64;

        float acc[4][4];
#pragma unroll
        for (int nf = 0; nf < 4; nf++)
#pragma unroll
            for (int u = 0; u < 4; u++) acc[nf][u] = 0.f;

#pragma unroll
        for (int ks = 0; ks < 12; ks++) {
            const int cb = ks * 32 + (lane >> 4) * 16;
            uint32_t a[4];
            ldmx4(a[0], a[1], a[2], a[3], sb + AQ3 + (wm + (lane & 15)) * 400 + cb);
            uint32_t bf[2][4];
#pragma unroll
            for (int nh = 0; nh < 2; nh++) {
                const int r = wn + nh * 16 + (lane & 15);
                ldmx4(bf[nh][0], bf[nh][1], bf[nh][2], bf[nh][3], kbuf + r * 400 + cb);
            }
#pragma unroll
            for (int nf = 0; nf < 4; nf++) {
                const uint32_t b0 = bf[nf >> 1][(nf & 1)];
                const uint32_t b1 = bf[nf >> 1][(nf & 1) + 2];
                mma16816(acc[nf], a, b0, b1);
            }
        }

        const int i0 = wm + qr, iabs0 = q0 + i0;
        const int i1 = i0 + 8,  iabs1 = iabs0 + 8;
#pragma unroll
        for (int nf = 0; nf < 4; nf++) {
#pragma unroll
            for (int cc = 0; cc < 2; cc++) {
                const int col = wn + nf * 8 + qc + cc;
                const int jabs = kb + col;
                const bool jok = (jabs >= 0) && (jabs < xl);
                const bool v0 = jok && (jabs - iabs0 <= 128) && (iabs0 - jabs <= 128);
                const bool v1 = jok && (jabs - iabs1 <= 128) && (iabs1 - jabs <= 128);
                Ss[i0 * 325 + c * 64 + col] = v0 ? acc[nf][cc] * 0.125f : -1e30f;
                Ss[i1 * 325 + c * 64 + col] = v1 ? acc[nf][cc + 2] * 0.125f : -1e30f;
            }
        }
        __syncthreads();
        if (c + 2 < 5) {
            const int jabs = kbase0 + (c + 2) * 64 + lrow;
            const bool valid = (jabs >= 0) && (jabs < S_);
            const char* ksrc = (const char*)K3 + ((size_t)(b * S_ + (valid ? jabs : 0)) * K3_ + h * 192) * 2;
            const uint32_t buf = sb + ((c & 1) ? AV3 : AK3);
            const uint32_t n = valid ? 16u : 0u;
#pragma unroll
            for (int u = 0; u < 6; u++)
                cp_async16z(buf + lrow * 400 + (lcs + u) * 16, ksrc + (lcs + u) * 16, n);
        }
        CP_COMMIT();
    }

    // ---- preload V chunks 0,1 (overlap with softmax) ----
#pragma unroll
    for (int c = 0; c < 2; c++) {
        const char* vsrc = (const char*)V3T + ((size_t)((b * 8 + h) * 64 + lrow) * 6912) * 2
                           + (size_t)(q0 + c * 64) * 6;
        const uint32_t buf = sb + (c ? AV3 : AK3);
#pragma unroll
        for (int u = 0; u < 6; u++)
            cp_async16(buf + lrow * 400 + (lcs + u) * 16, vsrc + (lcs + u) * 16);
        CP_COMMIT();
    }

    // ---- phase 2: softmax ----
    {
        for (int rr = 0; rr < 8; rr++) {
            const int i = wid * 8 + rr;
            float* row = Ss + i * 325;
            float vals[10];
            float m = -3.0e38f;
#pragma unroll
            for (int t = 0; t < 10; t++) {
                vals[t] = row[lane + 32 * t];
                m = fmaxf(m, vals[t]);
            }
#pragma unroll
            for (int o = 16; o; o >>= 1) m = fmaxf(m, __shfl_xor_sync(0xffffffffu, m, o));
            float l = 0.f;
#pragma unroll
            for (int t = 0; t < 10; t++) {
                const float p = __expf(vals[t] - m);
                row[lane + 32 * t] = p;
                l += p;
            }
#pragma unroll
            for (int o = 16; o; o >>= 1) l += __shfl_xor_sync(0xffffffffu, l, o);
            if (lane == 0) invl[i] = 1.0f / l;
        }
    }
    __syncthreads();

    // ---- phase 3: AV ----
    float oacc[4][4];
#pragma unroll
    for (int nf = 0; nf < 4; nf++)
#pragma unroll
        for (int u = 0; u < 4; u++) oacc[nf][u] = 0.f;

#pragma unroll
    for (int c = 0; c < 5; c++) {
        // build P3 chunk c into AQ3 (prev mma done per trailing sync)
        {
            const int row = tid & 63, jg = tid >> 6;
            const float* srow = Ss + row * 325 + c * 64 + jg * 16;
            uint32_t w[24];
#pragma unroll
            for (int t = 0; t < 8; t++) packA(srow[2 * t], srow[2 * t + 1], w + 3 * t);
            uint4* dst = (uint4*)(smc + AQ3 + row * 400 + jg * 96);
#pragma unroll
            for (int u = 0; u < 6; u++) dst[u] = ((uint4*)w)[u];
        }
        if (c < 4) { CP_WAIT(1); } else { CP_WAIT(0); }
        __syncthreads();

        const uint32_t vbuf = sb + ((c & 1) ? AV3 : AK3);
#pragma unroll
        for (int ks = 0; ks < 12; ks++) {
            const int cb = ks * 32 + (lane >> 4) * 16;
            uint32_t a[4];
            ldmx4(a[0], a[1], a[2], a[3], sb + AQ3 + (wm + (lane & 15)) * 400 + cb);
            uint32_t bf[2][4];
#pragma unroll
            for (int nh = 0; nh < 2; nh++) {
                const int r = wn + nh * 16 + (lane & 15);
                ldmx4(bf[nh][0], bf[nh][1], bf[nh][2], bf[nh][3], vbuf + r * 400 + cb);
            }
#pragma unroll
            for (int nf = 0; nf < 4; nf++) {
                const uint32_t b0 = bf[nf >> 1][(nf & 1)];
                const uint32_t b1 = bf[nf >> 1][(nf & 1) + 2];
                mma16816(oacc[nf], a, b0, b1);
            }
        }
        __syncthreads();
        if (c + 2 < 5) {
            const char* vsrc = (const char*)V3T + ((size_t)((b * 8 + h) * 64 + lrow) * 6912) * 2
                               + (size_t)(q0 + (c + 2) * 64) * 6;
            const uint32_t buf = sb + ((c & 1) ? AV3 : AK3);
#pragma unroll
            for (int u = 0; u < 6; u++)
                cp_async16(buf + lrow * 400 + (lcs + u) * 16, vsrc + (lcs + u) * 16);
        }
        CP_COMMIT();
    }

    // ---- final write: normalize, triplet-pack into C3 (pattern A), deg override ----
    {
        const int i0 = wm + qr;
#pragma unroll
        for (int half = 0; half < 2; half++) {
            const int i = i0 + half * 8;
            const int iabs = q0 + i;
            int lo2 = iabs - 128;
            if (lo2 < 0) lo2 = 0;
            const bool deg = (lo2 >= xl);
            const float il = invl[i];
            uint32_t* crow = (uint32_t*)((char*)C3 + ((size_t)(b * S_ + iabs) * K3_ + h * 192) * 2);
            const float* vm = VMEAN + b * 512 + h * 64;
#pragma unroll
            for (int nf = 0; nf < 4; nf++) {
                const int col = wn + nf * 8 + qc;
                const float a = deg ? vm[col]     : oacc[nf][half * 2] * il;
                const float bb = deg ? vm[col + 1] : oacc[nf][half * 2 + 1] * il;
                uint32_t w[3];
                packA(a, bb, w);
                const uint32_t idx = (3 * col) / 2;
                crow[idx] = w[0]; crow[idx + 1] = w[1]; crow[idx + 2] = w[2];
            }
        }
    }
}

// ================= launch =================
extern "C" void kernel_launch(void* const* d_in, const int* in_sizes, int n_in,
                              void* d_out, int out_size) {
    const float* x  = (const float*)d_in[0];
    const float* Wq = (const float*)d_in[1];
    const float* bq = (const float*)d_in[2];
    const float* Wk = (const float*)d_in[3];
    const float* bk = (const float*)d_in[4];
    const float* Wv = (const float*)d_in[5];
    const float* bv = (const float*)d_in[6];
    const float* Wo = (const float*)d_in[7];
    const float* bo = (const float*)d_in[8];
    const int* xlen = (const int*)d_in[9];
    float* out = (float*)d_out;

    float *v, *part, *vmean;
    __nv_bfloat16 *x3, *q3, *k3, *w3t, *v3t;
    cudaGetSymbolAddress((void**)&v, g_v);
    cudaGetSymbolAddress((void**)&part, g_part);
    cudaGetSymbolAddress((void**)&vmean, g_vmean);
    cudaGetSymbolAddress((void**)&x3, g_x3);
    cudaGetSymbolAddress((void**)&q3, g_q3);
    cudaGetSymbolAddress((void**)&k3, g_k3);
    cudaGetSymbolAddress((void**)&w3t, g_w3t);
    cudaGetSymbolAddress((void**)&v3t, g_v3t);

    cudaFuncSetAttribute(gemm_mma, cudaFuncAttributeMaxDynamicSharedMemorySize, GEMM_SMEM);
    cudaFuncSetAttribute(gemm_tri<0>, cudaFuncAttributeMaxDynamicSharedMemorySize, GEMM_SMEM);
    cudaFuncSetAttribute(gemm_tri<1>, cudaFuncAttributeMaxDynamicSharedMemorySize, GEMM_SMEM);
    cudaFuncSetAttribute(attn_mma2, cudaFuncAttributeMaxDynamicSharedMemorySize, ATT_SMEM);

    const dim3 gemm_grid(B_ * S_ / 128, DM_ / 128);
    const size_t WSTRIDE = (size_t)DM_ * K3_;

    split_act3<<<B_ * S_ * 64 / 256, 256>>>(x, x3);
    split_w4<<<dim3(16, 16, 4), dim3(32, 32)>>>(Wq, Wk, Wv, Wo, w3t);

    gemm_tri<0><<<gemm_grid, 256, GEMM_SMEM>>>(x3, w3t, bq, q3);
    gemm_tri<1><<<gemm_grid, 256, GEMM_SMEM>>>(x3, w3t + WSTRIDE, bk, k3);
    gemm_mma<<<gemm_grid, 256, GEMM_SMEM>>>(x3, w3t + 2 * WSTRIDE, bv, v);

    v3t_build<<<dim3(36, H_, B_), 256>>>(v, v3t);
    vmean_partial<<<dim3(64, B_), DM_>>>(v, part);
    vmean_final<<<B_, DM_>>>(part, vmean);

    attn_mma2<<<dim3(S_ / 64, H_, B_), 256, ATT_SMEM>>>(q3, k3, v3t, vmean, xlen, x3);

    gemm_mma<<<gemm_grid, 256, GEMM_SMEM>>>(x3, w3t + 3 * WSTRIDE, bo, out);
}

// round 6
// speedup vs baseline: 1.4619x; 1.4619x over previous
#include <cuda_runtime.h>
#include <cuda_fp16.h>
#include <cstdint>

#define B_  4
#define S_  2048
#define DM_ 512
#define H_  8
#define D_  64
#define K2_ 1024            // 2x hi/lo expanded K
#define NCHUNK 16           // K2_/64

// ================= helpers =================
__device__ __forceinline__ uint32_t smem_u32(const void* p) {
    uint32_t a;
    asm("{ .reg .u64 t; cvta.to.shared.u64 t, %1; cvt.u32.u64 %0, t; }" : "=r"(a) : "l"(p));
    return a;
}
#define SWZ128(off) ((off) ^ (((off) >> 3) & 0x70))

__device__ __forceinline__ void cp_async16(uint32_t dst, const void* src) {
    asm volatile("cp.async.cg.shared.global [%0], [%1], 16;" :: "r"(dst), "l"(src));
}
__device__ __forceinline__ void cp_async16z(uint32_t dst, const void* src, uint32_t n) {
    asm volatile("cp.async.cg.shared.global [%0], [%1], 16, %2;" :: "r"(dst), "l"(src), "r"(n));
}
#define CP_COMMIT() asm volatile("cp.async.commit_group;" ::: "memory")
#define CP_WAIT(n)  asm volatile("cp.async.wait_group %0;" :: "n"(n) : "memory")

__device__ __forceinline__ void ldmx4(uint32_t& r0, uint32_t& r1, uint32_t& r2, uint32_t& r3,
                                      uint32_t addr) {
    asm volatile("ldmatrix.sync.aligned.m8n8.x4.shared.b16 {%0,%1,%2,%3}, [%4];"
                 : "=r"(r0), "=r"(r1), "=r"(r2), "=r"(r3) : "r"(addr));
}
__device__ __forceinline__ void mma16816(float* c, const uint32_t* a, uint32_t b0, uint32_t b1) {
    asm volatile(
        "mma.sync.aligned.m16n8k16.row.col.f32.f16.f16.f32 "
        "{%0,%1,%2,%3}, {%4,%5,%6,%7}, {%8,%9}, {%0,%1,%2,%3};"
        : "+f"(c[0]), "+f"(c[1]), "+f"(c[2]), "+f"(c[3])
        : "r"(a[0]), "r"(a[1]), "r"(a[2]), "r"(a[3]), "r"(b0), "r"(b1));
}
// A-side pair: (hi, lo)
__device__ __forceinline__ void pack2A(float a, float b, uint32_t* w) {
    const __half ha = __float2half_rn(a);
    const __half la = __float2half_rn(a - __half2float(ha));
    const __half hb = __float2half_rn(b);
    const __half lb = __float2half_rn(b - __half2float(hb));
    w[0] = (uint32_t)__half_as_ushort(ha) | ((uint32_t)__half_as_ushort(la) << 16);
    w[1] = (uint32_t)__half_as_ushort(hb) | ((uint32_t)__half_as_ushort(lb) << 16);
}
// B-side pair: (hi, hi)
__device__ __forceinline__ void pack2B(float a, float b, uint32_t* w) {
    const uint32_t ha = __half_as_ushort(__float2half_rn(a));
    const uint32_t hb = __half_as_ushort(__float2half_rn(b));
    w[0] = ha | (ha << 16);
    w[1] = hb | (hb << 16);
}

// ================= scratch =================
__device__ float g_v[B_ * S_ * DM_];
__device__ float g_part[B_ * 64 * DM_];
__device__ float g_vmean[B_ * DM_];
__device__ __half g_x2[B_ * S_ * K2_];        // x pairs (A), later ctx pairs (A)
__device__ __half g_q2[B_ * S_ * K2_];        // q pairs (A)
__device__ __half g_k2[B_ * S_ * K2_];        // k pairs (B)
__device__ __half g_w2t[4 * DM_ * K2_];       // weights (B), [N,K2]
__device__ __half g_v2t[2048 * 4608];         // V dims-major pairs (B), tokens padded [-128,2176)

// ================= split kernels =================
__global__ __launch_bounds__(256) void split_act2(const float* __restrict__ X,
                                                  __half* __restrict__ X2) {
    const int idx = blockIdx.x * 256 + threadIdx.x;
    const int m = idx >> 6, g = idx & 63;
    const float4 f0 = *(const float4*)(X + (size_t)m * 512 + g * 8);
    const float4 f1 = *(const float4*)(X + (size_t)m * 512 + g * 8 + 4);
    float v[8] = {f0.x, f0.y, f0.z, f0.w, f1.x, f1.y, f1.z, f1.w};
    uint32_t w[8];
#pragma unroll
    for (int i = 0; i < 4; i++) pack2A(v[2 * i], v[2 * i + 1], w + 2 * i);
    uint4* dst = (uint4*)(X2 + (size_t)m * K2_ + g * 16);
    dst[0] = ((uint4*)w)[0]; dst[1] = ((uint4*)w)[1];
}

__global__ __launch_bounds__(1024) void split_w4(const float* __restrict__ W0,
                                                 const float* __restrict__ W1,
                                                 const float* __restrict__ W2,
                                                 const float* __restrict__ W3,
                                                 __half* __restrict__ W2T) {
    __shared__ float t[32][33];
    const int z = blockIdx.z;
    const float* W = (z == 0) ? W0 : (z == 1) ? W1 : (z == 2) ? W2 : W3;
    const int k0 = blockIdx.y * 32, n0 = blockIdx.x * 32;
    const int tx = threadIdx.x, ty = threadIdx.y;
    t[ty][tx] = W[(size_t)(k0 + ty) * 512 + n0 + tx];
    __syncthreads();
    const float v = t[tx][ty];    // W[k0+tx][n0+ty]
    const uint32_t h = __half_as_ushort(__float2half_rn(v));
    uint32_t* dst = (uint32_t*)W2T + (size_t)z * DM_ * 512 + (size_t)(n0 + ty) * 512 + (k0 + tx);
    *dst = h | (h << 16);
}

// ================= HMMA GEMM: C[8192,512] = A2 @ B2^T (+bias) =================
// CTA 128x128, BK=64 fp16 (128B rows, SW128), 3-stage ring, prefetch-before-compute.
#define GEMM_SMEM (3 * 32768 + 1024)

#define GEMM_MAINLOOP()                                                                   \
    extern __shared__ char smraw[];                                                       \
    const uint32_t sbase = (smem_u32(smraw) + 1023) & ~1023u;                             \
    const int tid = threadIdx.x;                                                          \
    const int wid = tid >> 5, lane = tid & 31;                                            \
    const int bm = blockIdx.x * 128, bn = blockIdx.y * 128;                               \
    const int wm0 = (wid & 1) * 64, wn0 = (wid >> 1) * 32;                                \
    const int l_isB = tid >> 7;                                                           \
    const int l_row = (tid & 127);                                                        \
    const __half* l_src = (l_isB ? B2 + (size_t)(bn + l_row) * K2_                        \
                                 : A2 + (size_t)(bm + l_row) * K2_);                      \
    const uint32_t l_dst = sbase + (l_isB ? 16384 : 0);                                   \
    float acc[4][4][4];                                                                   \
    _Pragma("unroll")                                                                     \
    for (int a = 0; a < 4; a++)                                                           \
        _Pragma("unroll")                                                                 \
        for (int b = 0; b < 4; b++)                                                       \
            _Pragma("unroll")                                                             \
            for (int c = 0; c < 4; c++) acc[a][b][c] = 0.f;                               \
    _Pragma("unroll")                                                                     \
    for (int c = 0; c < 2; c++) {                                                         \
        const uint32_t db = l_dst + c * 32768;                                            \
        const __half* sp = l_src + c * 64;                                                \
        _Pragma("unroll")                                                                 \
        for (int seg = 0; seg < 8; seg++)                                                 \
            cp_async16(db + SWZ128(l_row * 128 + seg * 16), sp + seg * 8);                \
        CP_COMMIT();                                                                      \
    }                                                                                     \
    for (int c = 0; c < NCHUNK; c++) {                                                    \
        CP_WAIT(1);                                                                       \
        __syncthreads();                                                                  \
        if (c + 2 < NCHUNK) {                                                             \
            const uint32_t db = l_dst + ((c + 2) % 3) * 32768;                            \
            const __half* sp = l_src + (c + 2) * 64;                                      \
            _Pragma("unroll")                                                             \
            for (int seg = 0; seg < 8; seg++)                                             \
                cp_async16(db + SWZ128(l_row * 128 + seg * 16), sp + seg * 8);            \
        }                                                                                 \
        CP_COMMIT();                                                                      \
        const uint32_t abuf = sbase + (c % 3) * 32768;                                    \
        const uint32_t bbuf = abuf + 16384;                                               \
        _Pragma("unroll")                                                                 \
        for (int ks = 0; ks < 4; ks++) {                                                  \
            const int cb = ks * 32 + ((lane >> 4) * 16);                                  \
            uint32_t bf[2][4];                                                            \
            _Pragma("unroll")                                                             \
            for (int nh = 0; nh < 2; nh++) {                                              \
                const int r = wn0 + nh * 16 + (lane & 15);                                \
                ldmx4(bf[nh][0], bf[nh][1], bf[nh][2], bf[nh][3],                         \
                      bbuf + SWZ128(r * 128 + cb));                                       \
            }                                                                             \
            _Pragma("unroll")                                                             \
            for (int mf = 0; mf < 4; mf++) {                                              \
                uint32_t a[4];                                                            \
                const int r = wm0 + mf * 16 + (lane & 15);                                \
                ldmx4(a[0], a[1], a[2], a[3], abuf + SWZ128(r * 128 + cb));               \
                _Pragma("unroll")                                                         \
                for (int nf = 0; nf < 4; nf++) {                                          \
                    const uint32_t b0 = bf[nf >> 1][(nf & 1)];                            \
                    const uint32_t b1 = bf[nf >> 1][(nf & 1) + 2];                        \
                    mma16816(acc[mf][nf], a, b0, b1);                                     \
                }                                                                         \
            }                                                                             \
        }                                                                                 \
    }                                                                                     \
    const int qr = lane >> 2, qc = (lane & 3) * 2;

// fp32 output (V projection, final output projection)
__global__ __launch_bounds__(256, 2) void gemm_mma(const __half* __restrict__ A2,
                                                   const __half* __restrict__ B2,
                                                   const float* __restrict__ bias,
                                                   float* __restrict__ C) {
    GEMM_MAINLOOP()
#pragma unroll
    for (int mf = 0; mf < 4; mf++) {
        const int row = bm + wm0 + mf * 16 + qr;
#pragma unroll
        for (int nf = 0; nf < 4; nf++) {
            const int col = bn + wn0 + nf * 8 + qc;
            const float b0 = bias[col], b1 = bias[col + 1];
            float2 lo, hi;
            lo.x = acc[mf][nf][0] + b0; lo.y = acc[mf][nf][1] + b1;
            hi.x = acc[mf][nf][2] + b0; hi.y = acc[mf][nf][3] + b1;
            *(float2*)(C + (size_t)row * 512 + col) = lo;
            *(float2*)(C + (size_t)(row + 8) * 512 + col) = hi;
        }
    }
}

// pair output: PAT 0 = A pattern (hi,lo) for Q; PAT 1 = B pattern (hi,hi) for K
template<int PAT>
__global__ __launch_bounds__(256, 2) void gemm_pair(const __half* __restrict__ A2,
                                                    const __half* __restrict__ B2,
                                                    const float* __restrict__ bias,
                                                    __half* __restrict__ T2) {
    GEMM_MAINLOOP()
    uint32_t* t32 = (uint32_t*)T2;
#pragma unroll
    for (int mf = 0; mf < 4; mf++) {
        const int row = bm + wm0 + mf * 16 + qr;
#pragma unroll
        for (int nf = 0; nf < 4; nf++) {
            const int col = bn + wn0 + nf * 8 + qc;
            const float b0 = bias[col], b1 = bias[col + 1];
            uint32_t w[2];
            const uint32_t idx0 = (uint32_t)row * 512 + col;
            const uint32_t idx1 = idx0 + 8 * 512;
            if (PAT == 0) pack2A(acc[mf][nf][0] + b0, acc[mf][nf][1] + b1, w);
            else          pack2B(acc[mf][nf][0] + b0, acc[mf][nf][1] + b1, w);
            t32[idx0] = w[0]; t32[idx0 + 1] = w[1];
            if (PAT == 0) pack2A(acc[mf][nf][2] + b0, acc[mf][nf][3] + b1, w);
            else          pack2B(acc[mf][nf][2] + b0, acc[mf][nf][3] + b1, w);
            t32[idx1] = w[0]; t32[idx1 + 1] = w[1];
        }
    }
}

// ================= V transpose->pair build (dims-major, token-padded) =================
__global__ __launch_bounds__(256) void v2t_build(const float* __restrict__ V,
                                                 __half* __restrict__ V2T) {
    __shared__ float tr[64][65];
    const int cx = blockIdx.x;           // 36 chunks of 64 tokens, token0 = cx*64-128
    const int h = blockIdx.y, b = blockIdx.z;
    const int tid = threadIdx.x;
    const int t0 = cx * 64 - 128;
    const bool inr = (t0 >= 0) && (t0 + 64 <= S_);

    if (inr) {
        const int i = tid >> 2, dg = tid & 3;
        const float* vrow = V + ((size_t)(b * S_ + t0 + i)) * DM_ + h * D_ + dg * 16;
#pragma unroll
        for (int u = 0; u < 4; u++) {
            float4 f = *(const float4*)(vrow + u * 4);
            tr[dg * 16 + u * 4 + 0][i] = f.x;
            tr[dg * 16 + u * 4 + 1][i] = f.y;
            tr[dg * 16 + u * 4 + 2][i] = f.z;
            tr[dg * 16 + u * 4 + 3][i] = f.w;
        }
        __syncthreads();
    }

    const int d = tid >> 2, jg = tid & 3;   // jg: 16 tokens each
    uint32_t w[16];
    if (inr) {
#pragma unroll
        for (int t = 0; t < 8; t++)
            pack2B(tr[d][jg * 16 + 2 * t], tr[d][jg * 16 + 2 * t + 1], w + 2 * t);
    } else {
#pragma unroll
        for (int t = 0; t < 16; t++) w[t] = 0;
    }
    uint4* dst = (uint4*)((char*)V2T + ((size_t)((b * 8 + h) * 64 + d) * 4608) * 2
                          + (size_t)cx * 256 + jg * 64);
#pragma unroll
    for (int u = 0; u < 4; u++) dst[u] = ((uint4*)w)[u];
}

// ================= V mean =================
__global__ void vmean_partial(const float* __restrict__ V, float* __restrict__ part) {
    const int b = blockIdx.y, sc = blockIdx.x, c = threadIdx.x;
    const float* p = V + ((size_t)b * S_ + sc * 32) * DM_ + c;
    float s = 0.f;
#pragma unroll 8
    for (int t = 0; t < 32; t++) s += p[(size_t)t * DM_];
    part[((size_t)b * 64 + sc) * DM_ + c] = s;
}
__global__ void vmean_final(const float* __restrict__ part, float* __restrict__ vm) {
    const int b = blockIdx.x, c = threadIdx.x;
    const float* p = part + (size_t)b * 64 * DM_ + c;
    float s = 0.f;
#pragma unroll
    for (int t = 0; t < 64; t++) s += p[(size_t)t * DM_];
    vm[b * DM_ + c] = s * (1.0f / 2048.0f);
}

// ================= HMMA banded attention (fp16 pairs) =================
// smem rows: 128 fp16 = 256B data, stride 272B (17x16B, ldmatrix conflict-free)
#define AQ2 0
#define AK2 17408
#define AV2 34816
#define ASF 52224
#define AIL 135424
#define ATT_SMEM 135680

__global__ __launch_bounds__(256, 1) void attn_mma2(const __half* __restrict__ Q2,
                                                    const __half* __restrict__ K2,
                                                    const __half* __restrict__ V2T,
                                                    const float* __restrict__ VMEAN,
                                                    const int* __restrict__ XLEN,
                                                    __half* __restrict__ C2) {
    extern __shared__ char smc[];
    const uint32_t sb = smem_u32(smc);
    float* Ss = (float*)(smc + ASF);
    float* invl = (float*)(smc + AIL);

    const int tid = threadIdx.x;
    const int wid = tid >> 5, lane = tid & 31;
    const int q0 = blockIdx.x * 64;
    const int h = blockIdx.y;
    const int b = blockIdx.z;
    const int xl = XLEN[b];

    const int wm = (wid & 3) * 16;
    const int wn = (wid >> 2) * 32;
    const int qr = lane >> 2, qc = (lane & 3) * 2;
    const int kbase0 = q0 - 128;

    const int lrow = tid >> 2;            // 0..63
    const int lcs = (tid & 3) * 4;        // 4 segs of 16B each

    // ---- issue Q2 + K0 (group0), K1 (group1) ----
    {
        const char* qsrc = (const char*)Q2 + ((size_t)(b * S_ + q0 + lrow) * K2_ + h * 128) * 2;
#pragma unroll
        for (int u = 0; u < 4; u++)
            cp_async16(sb + AQ2 + lrow * 272 + (lcs + u) * 16, qsrc + (lcs + u) * 16);
    }
#pragma unroll
    for (int c = 0; c < 2; c++) {
        const int jabs = kbase0 + c * 64 + lrow;
        const bool valid = (jabs >= 0) && (jabs < S_);
        const char* ksrc = (const char*)K2 + ((size_t)(b * S_ + (valid ? jabs : 0)) * K2_ + h * 128) * 2;
        const uint32_t buf = sb + (c ? AV2 : AK2);
        const uint32_t n = valid ? 16u : 0u;
#pragma unroll
        for (int u = 0; u < 4; u++)
            cp_async16z(buf + lrow * 272 + (lcs + u) * 16, ksrc + (lcs + u) * 16, n);
        CP_COMMIT();
    }

    // ---- phase 1: energies ----
#pragma unroll
    for (int c = 0; c < 5; c++) {
        if (c < 4) { CP_WAIT(1); } else { CP_WAIT(0); }
        __syncthreads();
        const uint32_t kbuf = sb + ((c & 1) ? AV2 : AK2);
        const int kb = kbase0 + c * 64;

        float acc[4][4];
#pragma unroll
        for (int nf = 0; nf < 4; nf++)
#pragma unroll
            for (int u = 0; u < 4; u++) acc[nf][u] = 0.f;

#pragma unroll
        for (int ks = 0; ks < 8; ks++) {
            const int cb = ks * 32 + (lane >> 4) * 16;
            uint32_t a[4];
            ldmx4(a[0], a[1], a[2], a[3], sb + AQ2 + (wm + (lane & 15)) * 272 + cb);
            uint32_t bf[2][4];
#pragma unroll
            for (int nh = 0; nh < 2; nh++) {
                const int r = wn + nh * 16 + (lane & 15);
                ldmx4(bf[nh][0], bf[nh][1], bf[nh][2], bf[nh][3], kbuf + r * 272 + cb);
            }
#pragma unroll
            for (int nf = 0; nf < 4; nf++) {
                const uint32_t b0 = bf[nf >> 1][(nf & 1)];
                const uint32_t b1 = bf[nf >> 1][(nf & 1) + 2];
                mma16816(acc[nf], a, b0, b1);
            }
        }

        const int i0 = wm + qr, iabs0 = q0 + i0;
        const int i1 = i0 + 8,  iabs1 = iabs0 + 8;
#pragma unroll
        for (int nf = 0; nf < 4; nf++) {
#pragma unroll
            for (int cc = 0; cc < 2; cc++) {
                const int col = wn + nf * 8 + qc + cc;
                const int jabs = kb + col;
                const bool jok = (jabs >= 0) && (jabs < xl);
                const bool v0 = jok && (jabs - iabs0 <= 128) && (iabs0 - jabs <= 128);
                const bool v1 = jok && (jabs - iabs1 <= 128) && (iabs1 - jabs <= 128);
                Ss[i0 * 325 + c * 64 + col] = v0 ? acc[nf][cc] * 0.125f : -1e30f;
                Ss[i1 * 325 + c * 64 + col] = v1 ? acc[nf][cc + 2] * 0.125f : -1e30f;
            }
        }
        __syncthreads();
        if (c + 2 < 5) {
            const int jabs = kbase0 + (c + 2) * 64 + lrow;
            const bool valid = (jabs >= 0) && (jabs < S_);
            const char* ksrc = (const char*)K2 + ((size_t)(b * S_ + (valid ? jabs : 0)) * K2_ + h * 128) * 2;
            const uint32_t buf = sb + ((c & 1) ? AV2 : AK2);
            const uint32_t n = valid ? 16u : 0u;
#pragma unroll
            for (int u = 0; u < 4; u++)
                cp_async16z(buf + lrow * 272 + (lcs + u) * 16, ksrc + (lcs + u) * 16, n);
        }
        CP_COMMIT();
    }

    // ---- preload V chunks 0,1 (overlap with softmax) ----
#pragma unroll
    for (int c = 0; c < 2; c++) {
        const char* vsrc = (const char*)V2T + ((size_t)((b * 8 + h) * 64 + lrow) * 4608) * 2
                           + (size_t)(q0 + c * 64) * 4;
        const uint32_t buf = sb + (c ? AV2 : AK2);
#pragma unroll
        for (int u = 0; u < 4; u++)
            cp_async16(buf + lrow * 272 + (lcs + u) * 16, vsrc + (lcs + u) * 16);
        CP_COMMIT();
    }

    // ---- phase 2: softmax ----
    {
        for (int rr = 0; rr < 8; rr++) {
            const int i = wid * 8 + rr;
            float* row = Ss + i * 325;
            float vals[10];
            float m = -3.0e38f;
#pragma unroll
            for (int t = 0; t < 10; t++) {
                vals[t] = row[lane + 32 * t];
                m = fmaxf(m, vals[t]);
            }
#pragma unroll
            for (int o = 16; o; o >>= 1) m = fmaxf(m, __shfl_xor_sync(0xffffffffu, m, o));
            float l = 0.f;
#pragma unroll
            for (int t = 0; t < 10; t++) {
                const float p = __expf(vals[t] - m);
                row[lane + 32 * t] = p;
                l += p;
            }
#pragma unroll
            for (int o = 16; o; o >>= 1) l += __shfl_xor_sync(0xffffffffu, l, o);
            if (lane == 0) invl[i] = 1.0f / l;
        }
    }
    __syncthreads();

    // ---- phase 3: AV ----
    float oacc[4][4];
#pragma unroll
    for (int nf = 0; nf < 4; nf++)
#pragma unroll
        for (int u = 0; u < 4; u++) oacc[nf][u] = 0.f;

#pragma unroll
    for (int c = 0; c < 5; c++) {
        // build P2 chunk c into AQ2 (prev iter's trailing sync protects)
        {
            const int row = tid & 63, jg = tid >> 6;
            const float* srow = Ss + row * 325 + c * 64 + jg * 16;
            uint32_t w[16];
#pragma unroll
            for (int t = 0; t < 8; t++) pack2A(srow[2 * t], srow[2 * t + 1], w + 2 * t);
            uint4* dst = (uint4*)(smc + AQ2 + row * 272 + jg * 64);
#pragma unroll
            for (int u = 0; u < 4; u++) dst[u] = ((uint4*)w)[u];
        }
        if (c < 4) { CP_WAIT(1); } else { CP_WAIT(0); }
        __syncthreads();

        const uint32_t vbuf = sb + ((c & 1) ? AV2 : AK2);
#pragma unroll
        for (int ks = 0; ks < 8; ks++) {
            const int cb = ks * 32 + (lane >> 4) * 16;
            uint32_t a[4];
            ldmx4(a[0], a[1], a[2], a[3], sb + AQ2 + (wm + (lane & 15)) * 272 + cb);
            uint32_t bf[2][4];
#pragma unroll
            for (int nh = 0; nh < 2; nh++) {
                const int r = wn + nh * 16 + (lane & 15);
                ldmx4(bf[nh][0], bf[nh][1], bf[nh][2], bf[nh][3], vbuf + r * 272 + cb);
            }
#pragma unroll
            for (int nf = 0; nf < 4; nf++) {
                const uint32_t b0 = bf[nf >> 1][(nf & 1)];
                const uint32_t b1 = bf[nf >> 1][(nf & 1) + 2];
                mma16816(oacc[nf], a, b0, b1);
            }
        }
        __syncthreads();
        if (c + 2 < 5) {
            const char* vsrc = (const char*)V2T + ((size_t)((b * 8 + h) * 64 + lrow) * 4608) * 2
                               + (size_t)(q0 + (c + 2) * 64) * 4;
            const uint32_t buf = sb + ((c & 1) ? AV2 : AK2);
#pragma unroll
            for (int u = 0; u < 4; u++)
                cp_async16(buf + lrow * 272 + (lcs + u) * 16, vsrc + (lcs + u) * 16);
        }
        CP_COMMIT();
    }

    // ---- final write: normalize, pack pairs (A pattern) into C2, deg override ----
    {
        const int i0 = wm + qr;
#pragma unroll
        for (int half = 0; half < 2; half++) {
            const int i = i0 + half * 8;
            const int iabs = q0 + i;
            int lo2 = iabs - 128;
            if (lo2 < 0) lo2 = 0;
            const bool deg = (lo2 >= xl);
            const float il = invl[i];
            uint32_t* crow = (uint32_t*)C2 + (size_t)(b * S_ + iabs) * 512 + h * 64;
            const float* vm = VMEAN + b * 512 + h * 64;
#pragma unroll
            for (int nf = 0; nf < 4; nf++) {
                const int col = wn + nf * 8 + qc;
                const float a = deg ? vm[col]      : oacc[nf][half * 2] * il;
                const float bb = deg ? vm[col + 1] : oacc[nf][half * 2 + 1] * il;
                uint32_t w[2];
                pack2A(a, bb, w);
                crow[col] = w[0]; crow[col + 1] = w[1];
            }
        }
    }
}

// ================= launch =================
extern "C" void kernel_launch(void* const* d_in, const int* in_sizes, int n_in,
                              void* d_out, int out_size) {
    const float* x  = (const float*)d_in[0];
    const float* Wq = (const float*)d_in[1];
    const float* bq = (const float*)d_in[2];
    const float* Wk = (const float*)d_in[3];
    const float* bk = (const float*)d_in[4];
    const float* Wv = (const float*)d_in[5];
    const float* bv = (const float*)d_in[6];
    const float* Wo = (const float*)d_in[7];
    const float* bo = (const float*)d_in[8];
    const int* xlen = (const int*)d_in[9];
    float* out = (float*)d_out;

    float *v, *part, *vmean;
    __half *x2, *q2, *k2, *w2t, *v2t;
    cudaGetSymbolAddress((void**)&v, g_v);
    cudaGetSymbolAddress((void**)&part, g_part);
    cudaGetSymbolAddress((void**)&vmean, g_vmean);
    cudaGetSymbolAddress((void**)&x2, g_x2);
    cudaGetSymbolAddress((void**)&q2, g_q2);
    cudaGetSymbolAddress((void**)&k2, g_k2);
    cudaGetSymbolAddress((void**)&w2t, g_w2t);
    cudaGetSymbolAddress((void**)&v2t, g_v2t);

    cudaFuncSetAttribute(gemm_mma, cudaFuncAttributeMaxDynamicSharedMemorySize, GEMM_SMEM);
    cudaFuncSetAttribute(gemm_pair<0>, cudaFuncAttributeMaxDynamicSharedMemorySize, GEMM_SMEM);
    cudaFuncSetAttribute(gemm_pair<1>, cudaFuncAttributeMaxDynamicSharedMemorySize, GEMM_SMEM);
    cudaFuncSetAttribute(attn_mma2, cudaFuncAttributeMaxDynamicSharedMemorySize, ATT_SMEM);

    const dim3 gemm_grid(B_ * S_ / 128, DM_ / 128);
    const size_t WSTRIDE = (size_t)DM_ * K2_;

    split_act2<<<B_ * S_ * 64 / 256, 256>>>(x, x2);
    split_w4<<<dim3(16, 16, 4), dim3(32, 32)>>>(Wq, Wk, Wv, Wo, w2t);

    gemm_pair<0><<<gemm_grid, 256, GEMM_SMEM>>>(x2, w2t, bq, q2);
    gemm_pair<1><<<gemm_grid, 256, GEMM_SMEM>>>(x2, w2t + WSTRIDE, bk, k2);
    gemm_mma<<<gemm_grid, 256, GEMM_SMEM>>>(x2, w2t + 2 * WSTRIDE, bv, v);

    v2t_build<<<dim3(36, H_, B_), 256>>>(v, v2t);
    vmean_partial<<<dim3(64, B_), DM_>>>(v, part);
    vmean_final<<<B_, DM_>>>(part, vmean);

    attn_mma2<<<dim3(S_ / 64, H_, B_), 256, ATT_SMEM>>>(q2, k2, v2t, vmean, xlen, x2);

    gemm_mma<<<gemm_grid, 256, GEMM_SMEM>>>(x2, w2t + 3 * WSTRIDE, bo, out);
}

// round 7
// speedup vs baseline: 1.6578x; 1.1340x over previous
#include <cuda_runtime.h>
#include <cuda_fp16.h>
#include <cstdint>

#define B_  4
#define S_  2048
#define DM_ 512
#define H_  8
#define D_  64
#define K2_ 1024            // 2x hi/lo expanded K
#define NCHUNK 16           // K2_/64

// ================= helpers =================
__device__ __forceinline__ uint32_t smem_u32(const void* p) {
    uint32_t a;
    asm("{ .reg .u64 t; cvta.to.shared.u64 t, %1; cvt.u32.u64 %0, t; }" : "=r"(a) : "l"(p));
    return a;
}
#define SWZ128(off) ((off) ^ (((off) >> 3) & 0x70))

__device__ __forceinline__ void cp_async16(uint32_t dst, const void* src) {
    asm volatile("cp.async.cg.shared.global [%0], [%1], 16;" :: "r"(dst), "l"(src));
}
__device__ __forceinline__ void cp_async16z(uint32_t dst, const void* src, uint32_t n) {
    asm volatile("cp.async.cg.shared.global [%0], [%1], 16, %2;" :: "r"(dst), "l"(src), "r"(n));
}
#define CP_COMMIT() asm volatile("cp.async.commit_group;" ::: "memory")
#define CP_WAIT(n)  asm volatile("cp.async.wait_group %0;" :: "n"(n) : "memory")

__device__ __forceinline__ void ldmx4(uint32_t& r0, uint32_t& r1, uint32_t& r2, uint32_t& r3,
                                      uint32_t addr) {
    asm volatile("ldmatrix.sync.aligned.m8n8.x4.shared.b16 {%0,%1,%2,%3}, [%4];"
                 : "=r"(r0), "=r"(r1), "=r"(r2), "=r"(r3) : "r"(addr));
}
__device__ __forceinline__ void mma16816(float* c, const uint32_t* a, uint32_t b0, uint32_t b1) {
    asm volatile(
        "mma.sync.aligned.m16n8k16.row.col.f32.f16.f16.f32 "
        "{%0,%1,%2,%3}, {%4,%5,%6,%7}, {%8,%9}, {%0,%1,%2,%3};"
        : "+f"(c[0]), "+f"(c[1]), "+f"(c[2]), "+f"(c[3])
        : "r"(a[0]), "r"(a[1]), "r"(a[2]), "r"(a[3]), "r"(b0), "r"(b1));
}
// A-side pair: (hi, lo)
__device__ __forceinline__ void pack2A(float a, float b, uint32_t* w) {
    const __half ha = __float2half_rn(a);
    const __half la = __float2half_rn(a - __half2float(ha));
    const __half hb = __float2half_rn(b);
    const __half lb = __float2half_rn(b - __half2float(hb));
    w[0] = (uint32_t)__half_as_ushort(ha) | ((uint32_t)__half_as_ushort(la) << 16);
    w[1] = (uint32_t)__half_as_ushort(hb) | ((uint32_t)__half_as_ushort(lb) << 16);
}
// B-side pair: (hi, hi)
__device__ __forceinline__ void pack2B(float a, float b, uint32_t* w) {
    const uint32_t ha = __half_as_ushort(__float2half_rn(a));
    const uint32_t hb = __half_as_ushort(__float2half_rn(b));
    w[0] = ha | (ha << 16);
    w[1] = hb | (hb << 16);
}

// ================= scratch =================
__device__ float g_v[B_ * S_ * DM_];
__device__ float g_part[B_ * 64 * DM_];
__device__ float g_vmean[B_ * DM_];
__device__ __half g_x2[B_ * S_ * K2_];        // x pairs (A), later ctx pairs (A)
__device__ __half g_q2[B_ * S_ * K2_];        // q pairs (A)
__device__ __half g_k2[B_ * S_ * K2_];        // k pairs (B)
__device__ __half g_w2t[4 * DM_ * K2_];       // weights (B), [N,K2]
__device__ __half g_v2t[2048 * 4608];         // V dims-major pairs (B), tokens padded

// ================= split kernels =================
__global__ __launch_bounds__(256) void split_act2(const float* __restrict__ X,
                                                  __half* __restrict__ X2) {
    const int idx = blockIdx.x * 256 + threadIdx.x;
    const int m = idx >> 6, g = idx & 63;
    const float4 f0 = *(const float4*)(X + (size_t)m * 512 + g * 8);
    const float4 f1 = *(const float4*)(X + (size_t)m * 512 + g * 8 + 4);
    float v[8] = {f0.x, f0.y, f0.z, f0.w, f1.x, f1.y, f1.z, f1.w};
    uint32_t w[8];
#pragma unroll
    for (int i = 0; i < 4; i++) pack2A(v[2 * i], v[2 * i + 1], w + 2 * i);
    uint4* dst = (uint4*)(X2 + (size_t)m * K2_ + g * 16);
    dst[0] = ((uint4*)w)[0]; dst[1] = ((uint4*)w)[1];
}

__global__ __launch_bounds__(1024) void split_w4(const float* __restrict__ W0,
                                                 const float* __restrict__ W1,
                                                 const float* __restrict__ W2,
                                                 const float* __restrict__ W3,
                                                 __half* __restrict__ W2T) {
    __shared__ float t[32][33];
    const int z = blockIdx.z;
    const float* W = (z == 0) ? W0 : (z == 1) ? W1 : (z == 2) ? W2 : W3;
    const int k0 = blockIdx.y * 32, n0 = blockIdx.x * 32;
    const int tx = threadIdx.x, ty = threadIdx.y;
    t[ty][tx] = W[(size_t)(k0 + ty) * 512 + n0 + tx];
    __syncthreads();
    const float v = t[tx][ty];
    const uint32_t h = __half_as_ushort(__float2half_rn(v));
    uint32_t* dst = (uint32_t*)W2T + (size_t)z * DM_ * 512 + (size_t)(n0 + ty) * 512 + (k0 + tx);
    *dst = h | (h << 16);
}

// ================= 256x128 HMMA GEMM mainloop =================
// CTA tile M=256, N=128, BK=64, 3-stage ring (48KB/stage), 8 warps each 64x64.
#define GEMM_SMEM (3 * 49152 + 1024)

#define GEMM_MAINLOOP256(A2, B2)                                                          \
    extern __shared__ char smraw[];                                                       \
    const uint32_t sbase = (smem_u32(smraw) + 1023) & ~1023u;                             \
    const int tid = threadIdx.x;                                                          \
    const int wid = tid >> 5, lane = tid & 31;                                            \
    const int bm = blockIdx.x * 256, bn = blockIdx.y * 128;                               \
    const int wm0 = (wid & 3) * 64, wn0 = (wid >> 2) * 64;                                \
    const __half* l_srcA = A2 + (size_t)(bm + tid) * K2_;                                 \
    const __half* l_srcB = B2 + (size_t)(bn + (tid >> 1)) * K2_ + (tid & 1) * 32;         \
    const uint32_t a_doff = SWZ128(tid * 128);                                            \
    const uint32_t b_doff = 49152 - 16384 + SWZ128((tid >> 1) * 128 + (tid & 1) * 64);    \
    float acc[4][8][4];                                                                   \
    _Pragma("unroll")                                                                     \
    for (int a = 0; a < 4; a++)                                                           \
        _Pragma("unroll")                                                                 \
        for (int b = 0; b < 8; b++)                                                       \
            _Pragma("unroll")                                                             \
            for (int c = 0; c < 4; c++) acc[a][b][c] = 0.f;                               \
    _Pragma("unroll")                                                                     \
    for (int c = 0; c < 2; c++) {                                                         \
        const uint32_t st = sbase + c * 49152;                                            \
        _Pragma("unroll")                                                                 \
        for (int seg = 0; seg < 8; seg++)                                                 \
            cp_async16(st + (a_doff ^ (seg * 16)), l_srcA + c * 64 + seg * 8);            \
        _Pragma("unroll")                                                                 \
        for (int u = 0; u < 4; u++)                                                       \
            cp_async16(st + (b_doff ^ (u * 16)), l_srcB + c * 64 + u * 8);                \
        CP_COMMIT();                                                                      \
    }                                                                                     \
    for (int c = 0; c < NCHUNK; c++) {                                                    \
        CP_WAIT(1);                                                                       \
        __syncthreads();                                                                  \
        if (c + 2 < NCHUNK) {                                                             \
            const uint32_t st = sbase + ((c + 2) % 3) * 49152;                            \
            _Pragma("unroll")                                                             \
            for (int seg = 0; seg < 8; seg++)                                             \
                cp_async16(st + (a_doff ^ (seg * 16)), l_srcA + (c + 2) * 64 + seg * 8);  \
            _Pragma("unroll")                                                             \
            for (int u = 0; u < 4; u++)                                                   \
                cp_async16(st + (b_doff ^ (u * 16)), l_srcB + (c + 2) * 64 + u * 8);      \
        }                                                                                 \
        CP_COMMIT();                                                                      \
        const uint32_t abuf = sbase + (c % 3) * 49152;                                    \
        const uint32_t bbuf = abuf + 32768;                                               \
        _Pragma("unroll")                                                                 \
        for (int ks = 0; ks < 4; ks++) {                                                  \
            const int cb = ks * 32 + ((lane >> 4) * 16);                                  \
            uint32_t bf[4][4];                                                            \
            _Pragma("unroll")                                                             \
            for (int bh = 0; bh < 4; bh++) {                                              \
                const int r = wn0 + bh * 16 + (lane & 15);                                \
                ldmx4(bf[bh][0], bf[bh][1], bf[bh][2], bf[bh][3],                         \
                      bbuf + SWZ128(r * 128 + cb));                                       \
            }                                                                             \
            _Pragma("unroll")                                                             \
            for (int mf = 0; mf < 4; mf++) {                                              \
                uint32_t a[4];                                                            \
                const int r = wm0 + mf * 16 + (lane & 15);                                \
                ldmx4(a[0], a[1], a[2], a[3], abuf + SWZ128(r * 128 + cb));               \
                _Pragma("unroll")                                                         \
                for (int nf = 0; nf < 8; nf++) {                                          \
                    const uint32_t b0 = bf[nf >> 1][(nf & 1)];                            \
                    const uint32_t b1 = bf[nf >> 1][(nf & 1) + 2];                        \
                    mma16816(acc[mf][nf], a, b0, b1);                                     \
                }                                                                         \
            }                                                                             \
        }                                                                                 \
    }                                                                                     \
    const int qr = lane >> 2, qc = (lane & 3) * 2;

// unified QKV: z=0 -> Q pairs(A), z=1 -> K pairs(B), z=2 -> V fp32
__global__ __launch_bounds__(256, 1) void gemm_qkv(const __half* __restrict__ A2,
                                                   const __half* __restrict__ W2T,
                                                   const float* __restrict__ bq,
                                                   const float* __restrict__ bk,
                                                   const float* __restrict__ bv,
                                                   __half* __restrict__ Q2,
                                                   __half* __restrict__ K2,
                                                   float* __restrict__ Vf) {
    const int z = blockIdx.z;
    const __half* B2 = W2T + (size_t)z * DM_ * K2_;
    GEMM_MAINLOOP256(A2, B2)
    const float* bias = (z == 0) ? bq : (z == 1) ? bk : bv;
    if (z == 2) {
#pragma unroll
        for (int mf = 0; mf < 4; mf++) {
            const int row = bm + wm0 + mf * 16 + qr;
#pragma unroll
            for (int nf = 0; nf < 8; nf++) {
                const int col = bn + wn0 + nf * 8 + qc;
                const float b0 = bias[col], b1 = bias[col + 1];
                float2 lo, hi;
                lo.x = acc[mf][nf][0] + b0; lo.y = acc[mf][nf][1] + b1;
                hi.x = acc[mf][nf][2] + b0; hi.y = acc[mf][nf][3] + b1;
                *(float2*)(Vf + (size_t)row * 512 + col) = lo;
                *(float2*)(Vf + (size_t)(row + 8) * 512 + col) = hi;
            }
        }
    } else {
        uint32_t* t32 = (uint32_t*)((z == 0) ? Q2 : K2);
#pragma unroll
        for (int mf = 0; mf < 4; mf++) {
            const int row = bm + wm0 + mf * 16 + qr;
#pragma unroll
            for (int nf = 0; nf < 8; nf++) {
                const int col = bn + wn0 + nf * 8 + qc;
                const float b0 = bias[col], b1 = bias[col + 1];
                uint32_t w[2];
                const uint32_t idx0 = (uint32_t)row * 512 + col;
                const uint32_t idx1 = idx0 + 8 * 512;
                if (z == 0) pack2A(acc[mf][nf][0] + b0, acc[mf][nf][1] + b1, w);
                else        pack2B(acc[mf][nf][0] + b0, acc[mf][nf][1] + b1, w);
                t32[idx0] = w[0]; t32[idx0 + 1] = w[1];
                if (z == 0) pack2A(acc[mf][nf][2] + b0, acc[mf][nf][3] + b1, w);
                else        pack2B(acc[mf][nf][2] + b0, acc[mf][nf][3] + b1, w);
                t32[idx1] = w[0]; t32[idx1 + 1] = w[1];
            }
        }
    }
}

// output projection: fp32 out
__global__ __launch_bounds__(256, 1) void gemm_out(const __half* __restrict__ A2,
                                                   const __half* __restrict__ B2,
                                                   const float* __restrict__ bias,
                                                   float* __restrict__ C) {
    GEMM_MAINLOOP256(A2, B2)
#pragma unroll
    for (int mf = 0; mf < 4; mf++) {
        const int row = bm + wm0 + mf * 16 + qr;
#pragma unroll
        for (int nf = 0; nf < 8; nf++) {
            const int col = bn + wn0 + nf * 8 + qc;
            const float b0 = bias[col], b1 = bias[col + 1];
            float2 lo, hi;
            lo.x = acc[mf][nf][0] + b0; lo.y = acc[mf][nf][1] + b1;
            hi.x = acc[mf][nf][2] + b0; hi.y = acc[mf][nf][3] + b1;
            *(float2*)(C + (size_t)row * 512 + col) = lo;
            *(float2*)(C + (size_t)(row + 8) * 512 + col) = hi;
        }
    }
}

// ================= V transpose->pair build =================
__global__ __launch_bounds__(256) void v2t_build(const float* __restrict__ V,
                                                 __half* __restrict__ V2T) {
    __shared__ float tr[64][65];
    const int cx = blockIdx.x;
    const int h = blockIdx.y, b = blockIdx.z;
    const int tid = threadIdx.x;
    const int t0 = cx * 64 - 128;
    const bool inr = (t0 >= 0) && (t0 + 64 <= S_);

    if (inr) {
        const int i = tid >> 2, dg = tid & 3;
        const float* vrow = V + ((size_t)(b * S_ + t0 + i)) * DM_ + h * D_ + dg * 16;
#pragma unroll
        for (int u = 0; u < 4; u++) {
            float4 f = *(const float4*)(vrow + u * 4);
            tr[dg * 16 + u * 4 + 0][i] = f.x;
            tr[dg * 16 + u * 4 + 1][i] = f.y;
            tr[dg * 16 + u * 4 + 2][i] = f.z;
            tr[dg * 16 + u * 4 + 3][i] = f.w;
        }
        __syncthreads();
    }

    const int d = tid >> 2, jg = tid & 3;
    uint32_t w[16];
    if (inr) {
#pragma unroll
        for (int t = 0; t < 8; t++)
            pack2B(tr[d][jg * 16 + 2 * t], tr[d][jg * 16 + 2 * t + 1], w + 2 * t);
    } else {
#pragma unroll
        for (int t = 0; t < 16; t++) w[t] = 0;
    }
    uint4* dst = (uint4*)((char*)V2T + ((size_t)((b * 8 + h) * 64 + d) * 4608) * 2
                          + (size_t)cx * 256 + jg * 64);
#pragma unroll
    for (int u = 0; u < 4; u++) dst[u] = ((uint4*)w)[u];
}

// ================= V mean =================
__global__ void vmean_partial(const float* __restrict__ V, float* __restrict__ part) {
    const int b = blockIdx.y, sc = blockIdx.x, c = threadIdx.x;
    const float* p = V + ((size_t)b * S_ + sc * 32) * DM_ + c;
    float s = 0.f;
#pragma unroll 8
    for (int t = 0; t < 32; t++) s += p[(size_t)t * DM_];
    part[((size_t)b * 64 + sc) * DM_ + c] = s;
}
__global__ void vmean_final(const float* __restrict__ part, float* __restrict__ vm) {
    const int b = blockIdx.x, c = threadIdx.x;
    const float* p = part + (size_t)b * 64 * DM_ + c;
    float s = 0.f;
#pragma unroll
    for (int t = 0; t < 64; t++) s += p[(size_t)t * DM_];
    vm[b * DM_ + c] = s * (1.0f / 2048.0f);
}

// ================= HMMA banded attention (fp16 pairs) =================
#define AQ2 0
#define AK2 17408
#define AV2 34816
#define ASF 52224
#define AIL 135424
#define ATT_SMEM 135680

__global__ __launch_bounds__(256, 1) void attn_mma2(const __half* __restrict__ Q2,
                                                    const __half* __restrict__ K2,
                                                    const __half* __restrict__ V2T,
                                                    const float* __restrict__ VMEAN,
                                                    const int* __restrict__ XLEN,
                                                    __half* __restrict__ C2) {
    extern __shared__ char smc[];
    const uint32_t sb = smem_u32(smc);
    float* Ss = (float*)(smc + ASF);
    float* invl = (float*)(smc + AIL);

    const int tid = threadIdx.x;
    const int wid = tid >> 5, lane = tid & 31;
    const int q0 = blockIdx.x * 64;
    const int h = blockIdx.y;
    const int b = blockIdx.z;
    const int xl = XLEN[b];

    const int wm = (wid & 3) * 16;
    const int wn = (wid >> 2) * 32;
    const int qr = lane >> 2, qc = (lane & 3) * 2;
    const int kbase0 = q0 - 128;

    const int lrow = tid >> 2;
    const int lcs = (tid & 3) * 4;

    {
        const char* qsrc = (const char*)Q2 + ((size_t)(b * S_ + q0 + lrow) * K2_ + h * 128) * 2;
#pragma unroll
        for (int u = 0; u < 4; u++)
            cp_async16(sb + AQ2 + lrow * 272 + (lcs + u) * 16, qsrc + (lcs + u) * 16);
    }
#pragma unroll
    for (int c = 0; c < 2; c++) {
        const int jabs = kbase0 + c * 64 + lrow;
        const bool valid = (jabs >= 0) && (jabs < S_);
        const char* ksrc = (const char*)K2 + ((size_t)(b * S_ + (valid ? jabs : 0)) * K2_ + h * 128) * 2;
        const uint32_t buf = sb + (c ? AV2 : AK2);
        const uint32_t n = valid ? 16u : 0u;
#pragma unroll
        for (int u = 0; u < 4; u++)
            cp_async16z(buf + lrow * 272 + (lcs + u) * 16, ksrc + (lcs + u) * 16, n);
        CP_COMMIT();
    }

#pragma unroll
    for (int c = 0; c < 5; c++) {
        if (c < 4) { CP_WAIT(1); } else { CP_WAIT(0); }
        __syncthreads();
        const uint32_t kbuf = sb + ((c & 1) ? AV2 : AK2);
        const int kb = kbase0 + c * 64;

        float acc[4][4];
#pragma unroll
        for (int nf = 0; nf < 4; nf++)
#pragma unroll
            for (int u = 0; u < 4; u++) acc[nf][u] = 0.f;

#pragma unroll
        for (int ks = 0; ks < 8; ks++) {
            const int cb = ks * 32 + (lane >> 4) * 16;
            uint32_t a[4];
            ldmx4(a[0], a[1], a[2], a[3], sb + AQ2 + (wm + (lane & 15)) * 272 + cb);
            uint32_t bf[2][4];
#pragma unroll
            for (int nh = 0; nh < 2; nh++) {
                const int r = wn + nh * 16 + (lane & 15);
                ldmx4(bf[nh][0], bf[nh][1], bf[nh][2], bf[nh][3], kbuf + r * 272 + cb);
            }
#pragma unroll
            for (int nf = 0; nf < 4; nf++) {
                const uint32_t b0 = bf[nf >> 1][(nf & 1)];
                const uint32_t b1 = bf[nf >> 1][(nf & 1) + 2];
                mma16816(acc[nf], a, b0, b1);
            }
        }

        const int i0 = wm + qr, iabs0 = q0 + i0;
        const int i1 = i0 + 8,  iabs1 = iabs0 + 8;
#pragma unroll
        for (int nf = 0; nf < 4; nf++) {
#pragma unroll
            for (int cc = 0; cc < 2; cc++) {
                const int col = wn + nf * 8 + qc + cc;
                const int jabs = kb + col;
                const bool jok = (jabs >= 0) && (jabs < xl);
                const bool v0 = jok && (jabs - iabs0 <= 128) && (iabs0 - jabs <= 128);
                const bool v1 = jok && (jabs - iabs1 <= 128) && (iabs1 - jabs <= 128);
                Ss[i0 * 325 + c * 64 + col] = v0 ? acc[nf][cc] * 0.125f : -1e30f;
                Ss[i1 * 325 + c * 64 + col] = v1 ? acc[nf][cc + 2] * 0.125f : -1e30f;
            }
        }
        __syncthreads();
        if (c + 2 < 5) {
            const int jabs = kbase0 + (c + 2) * 64 + lrow;
            const bool valid = (jabs >= 0) && (jabs < S_);
            const char* ksrc = (const char*)K2 + ((size_t)(b * S_ + (valid ? jabs : 0)) * K2_ + h * 128) * 2;
            const uint32_t buf = sb + ((c & 1) ? AV2 : AK2);
            const uint32_t n = valid ? 16u : 0u;
#pragma unroll
            for (int u = 0; u < 4; u++)
                cp_async16z(buf + lrow * 272 + (lcs + u) * 16, ksrc + (lcs + u) * 16, n);
        }
        CP_COMMIT();
    }

#pragma unroll
    for (int c = 0; c < 2; c++) {
        const char* vsrc = (const char*)V2T + ((size_t)((b * 8 + h) * 64 + lrow) * 4608) * 2
                           + (size_t)(q0 + c * 64) * 4;
        const uint32_t buf = sb + (c ? AV2 : AK2);
#pragma unroll
        for (int u = 0; u < 4; u++)
            cp_async16(buf + lrow * 272 + (lcs + u) * 16, vsrc + (lcs + u) * 16);
        CP_COMMIT();
    }

    {
        for (int rr = 0; rr < 8; rr++) {
            const int i = wid * 8 + rr;
            float* row = Ss + i * 325;
            float vals[10];
            float m = -3.0e38f;
#pragma unroll
            for (int t = 0; t < 10; t++) {
                vals[t] = row[lane + 32 * t];
                m = fmaxf(m, vals[t]);
            }
#pragma unroll
            for (int o = 16; o; o >>= 1) m = fmaxf(m, __shfl_xor_sync(0xffffffffu, m, o));
            float l = 0.f;
#pragma unroll
            for (int t = 0; t < 10; t++) {
                const float p = __expf(vals[t] - m);
                row[lane + 32 * t] = p;
                l += p;
            }
#pragma unroll
            for (int o = 16; o; o >>= 1) l += __shfl_xor_sync(0xffffffffu, l, o);
            if (lane == 0) invl[i] = 1.0f / l;
        }
    }
    __syncthreads();

    float oacc[4][4];
#pragma unroll
    for (int nf = 0; nf < 4; nf++)
#pragma unroll
        for (int u = 0; u < 4; u++) oacc[nf][u] = 0.f;

#pragma unroll
    for (int c = 0; c < 5; c++) {
        {
            const int row = tid & 63, jg = tid >> 6;
            const float* srow = Ss + row * 325 + c * 64 + jg * 16;
            uint32_t w[16];
#pragma unroll
            for (int t = 0; t < 8; t++) pack2A(srow[2 * t], srow[2 * t + 1], w + 2 * t);
            uint4* dst = (uint4*)(smc + AQ2 + row * 272 + jg * 64);
#pragma unroll
            for (int u = 0; u < 4; u++) dst[u] = ((uint4*)w)[u];
        }
        if (c < 4) { CP_WAIT(1); } else { CP_WAIT(0); }
        __syncthreads();

        const uint32_t vbuf = sb + ((c & 1) ? AV2 : AK2);
#pragma unroll
        for (int ks = 0; ks < 8; ks++) {
            const int cb = ks * 32 + (lane >> 4) * 16;
            uint32_t a[4];
            ldmx4(a[0], a[1], a[2], a[3], sb + AQ2 + (wm + (lane & 15)) * 272 + cb);
            uint32_t bf[2][4];
#pragma unroll
            for (int nh = 0; nh < 2; nh++) {
                const int r = wn + nh * 16 + (lane & 15);
                ldmx4(bf[nh][0], bf[nh][1], bf[nh][2], bf[nh][3], vbuf + r * 272 + cb);
            }
#pragma unroll
            for (int nf = 0; nf < 4; nf++) {
                const uint32_t b0 = bf[nf >> 1][(nf & 1)];
                const uint32_t b1 = bf[nf >> 1][(nf & 1) + 2];
                mma16816(oacc[nf], a, b0, b1);
            }
        }
        __syncthreads();
        if (c + 2 < 5) {
            const char* vsrc = (const char*)V2T + ((size_t)((b * 8 + h) * 64 + lrow) * 4608) * 2
                               + (size_t)(q0 + (c + 2) * 64) * 4;
            const uint32_t buf = sb + ((c & 1) ? AV2 : AK2);
#pragma unroll
            for (int u = 0; u < 4; u++)
                cp_async16(buf + lrow * 272 + (lcs + u) * 16, vsrc + (lcs + u) * 16);
        }
        CP_COMMIT();
    }

    {
        const int i0 = wm + qr;
#pragma unroll
        for (int half = 0; half < 2; half++) {
            const int i = i0 + half * 8;
            const int iabs = q0 + i;
            int lo2 = iabs - 128;
            if (lo2 < 0) lo2 = 0;
            const bool deg = (lo2 >= xl);
            const float il = invl[i];
            uint32_t* crow = (uint32_t*)C2 + (size_t)(b * S_ + iabs) * 512 + h * 64;
            const float* vm = VMEAN + b * 512 + h * 64;
#pragma unroll
            for (int nf = 0; nf < 4; nf++) {
                const int col = wn + nf * 8 + qc;
                const float a = deg ? vm[col]      : oacc[nf][half * 2] * il;
                const float bb = deg ? vm[col + 1] : oacc[nf][half * 2 + 1] * il;
                uint32_t w[2];
                pack2A(a, bb, w);
                crow[col] = w[0]; crow[col + 1] = w[1];
            }
        }
    }
}

// ================= launch =================
extern "C" void kernel_launch(void* const* d_in, const int* in_sizes, int n_in,
                              void* d_out, int out_size) {
    const float* x  = (const float*)d_in[0];
    const float* Wq = (const float*)d_in[1];
    const float* bq = (const float*)d_in[2];
    const float* Wk = (const float*)d_in[3];
    const float* bk = (const float*)d_in[4];
    const float* Wv = (const float*)d_in[5];
    const float* bv = (const float*)d_in[6];
    const float* Wo = (const float*)d_in[7];
    const float* bo = (const float*)d_in[8];
    const int* xlen = (const int*)d_in[9];
    float* out = (float*)d_out;

    float *v, *part, *vmean;
    __half *x2, *q2, *k2, *w2t, *v2t;
    cudaGetSymbolAddress((void**)&v, g_v);
    cudaGetSymbolAddress((void**)&part, g_part);
    cudaGetSymbolAddress((void**)&vmean, g_vmean);
    cudaGetSymbolAddress((void**)&x2, g_x2);
    cudaGetSymbolAddress((void**)&q2, g_q2);
    cudaGetSymbolAddress((void**)&k2, g_k2);
    cudaGetSymbolAddress((void**)&w2t, g_w2t);
    cudaGetSymbolAddress((void**)&v2t, g_v2t);

    cudaFuncSetAttribute(gemm_qkv, cudaFuncAttributeMaxDynamicSharedMemorySize, GEMM_SMEM);
    cudaFuncSetAttribute(gemm_out, cudaFuncAttributeMaxDynamicSharedMemorySize, GEMM_SMEM);
    cudaFuncSetAttribute(attn_mma2, cudaFuncAttributeMaxDynamicSharedMemorySize, ATT_SMEM);

    const dim3 qkv_grid(B_ * S_ / 256, DM_ / 128, 3);
    const dim3 out_grid(B_ * S_ / 256, DM_ / 128);

    split_act2<<<B_ * S_ * 64 / 256, 256>>>(x, x2);
    split_w4<<<dim3(16, 16, 4), dim3(32, 32)>>>(Wq, Wk, Wv, Wo, w2t);

    gemm_qkv<<<qkv_grid, 256, GEMM_SMEM>>>(x2, w2t, bq, bk, bv, q2, k2, v);

    v2t_build<<<dim3(36, H_, B_), 256>>>(v, v2t);
    vmean_partial<<<dim3(64, B_), DM_>>>(v, part);
    vmean_final<<<B_, DM_>>>(part, vmean);

    attn_mma2<<<dim3(S_ / 64, H_, B_), 256, ATT_SMEM>>>(q2, k2, v2t, vmean, xlen, x2);

    gemm_out<<<out_grid, 256, GEMM_SMEM>>>(x2, w2t + 3 * (size_t)DM_ * K2_, bo, out);
}